// round 5
// baseline (speedup 1.0000x reference)
#include <cuda_runtime.h>
#include <math.h>

#define N_PROJ 96
#define A2D    96
#define DET2D  192
#define HH     128
#define WW     128
#define ZD     128

// ---------------- scratch (device globals; no allocation allowed) ----------
__device__ float4 g_deriv[(N_PROJ * A2D * DET2D) / 4];   // 6.75 MB
__device__ float2 g_cb2[N_PROJ * HH * WW];               // paired layout, 12.6 MB
__device__ float2 g_beta[N_PROJ];                        // (cos, sin) per beta

// ---------------- K0: beta trig table --------------------------------------
__global__ void beta_kernel() {
    int t = threadIdx.x;
    if (t < N_PROJ) {
        float b = (float)t * (float)(2.0 * M_PI / 96.0);
        float s, c;
        sincosf(b, &s, &c);
        g_beta[t] = make_float2(c, s);
    }
}

// ---------------- K1: ws = sino*weight ; deriv along detector --------------
__global__ void __launch_bounds__(192) deriv_kernel(
    const float* __restrict__ sino, const float* __restrict__ wt)
{
    __shared__ float ws[DET2D];
    int row = blockIdx.x;          // 0 .. 96*96-1
    int d = threadIdx.x;           // 0 .. 191
    int idx = row * DET2D + d;
    ws[d] = sino[idx] * wt[idx];
    __syncthreads();
    float v;
    if (d == 0)            v = ws[1] - ws[0];
    else if (d == DET2D-1) v = ws[DET2D-1] - ws[DET2D-2];
    else                   v = 0.5f * (ws[d+1] - ws[d-1]);
    ((float*)g_deriv)[idx] = v;
}

// ---------------- K2: 2D fan backprojection + cosine weights ---------------
// All sample positions are provably in-bounds: pos in [5.7, 185.3].
__global__ void __launch_bounds__(256) bp2d_kernel()
{
    __shared__ float  sder[48 * DET2D];   // 36 KB: half the angles per phase
    __shared__ float2 strig[A2D];

    const int tid = threadIdx.x;
    const int p   = blockIdx.y;          // projection index
    const int y0  = blockIdx.x * 16;     // 16 image rows per CTA

    if (tid < A2D) {
        float th = (float)tid * (float)(M_PI / 96.0);
        float s, c;
        sincosf(th, &s, &c);
        strig[tid] = make_float2(c, s);
    }

    float acc[8], xsv[8], ysv[8];
#pragma unroll
    for (int k = 0; k < 8; k++) {
        int px = tid + k * 256;
        int x  = px & 127;
        int yy = y0 + (px >> 7);
        xsv[k] = (float)x  - 63.5f;
        ysv[k] = (float)yy - 63.5f;
        acc[k] = 0.f;
    }

    const float4* gsrc = g_deriv + p * (A2D * DET2D / 4);

    for (int ph = 0; ph < 2; ph++) {
        __syncthreads();
#pragma unroll
        for (int i = 0; i < 9; i++)
            ((float4*)sder)[tid + i * 256] = gsrc[ph * 2304 + tid + i * 256];
        __syncthreads();

        for (int a = 0; a < 48; a++) {
            float2 t2 = strig[ph * 48 + a];
            float ca = t2.x, sa = t2.y;
            const float* rowp = sder + a * DET2D;
#pragma unroll
            for (int k = 0; k < 8; k++) {
                float pos = fmaf(ca, xsv[k], fmaf(sa, ysv[k], 95.5f));
                int   i0  = __float2int_rd(pos);
                float f   = pos - (float)i0;
                float v0 = rowp[i0];
                float v1 = rowp[i0 + 1];
                acc[k] = fmaf(f, v1 - v0, acc[k] + v0);
            }
        }
    }

    float* cbf = (float*)g_cb2;
#pragma unroll
    for (int k = 0; k < 8; k++) {
        int px = tid + k * 256;
        int x  = px & 127;
        int yy = y0 + (px >> 7);
        float w3  = 1000.0f / sqrtf(1.0e6f + xsv[k]*xsv[k] + ysv[k]*ysv[k]);
        float val = acc[k] * w3;
        int idx = (p * HH + yy) * WW + x;
        cbf[2 * idx] = val;                 // pair[x].x = v[x]
        if (x > 0)    cbf[2 * idx - 1] = val;   // pair[x-1].y = v[x]
        if (x == 127) cbf[2 * idx + 1] = 0.f;   // never read; keep defined
    }
}

// ---------------- K3: 3D cone-beam backprojection + PReLU ------------------
// pu in [11.3,115.7], pv in [19.2,107.7]: mask/clamp free; iu1=iu0+1, iv1=iv0+1.
// 8 z-planes per thread, 2048 CTAs -> ~12 CTAs/SM (75% occ), per-beta slice
// (131 KB) stays L1-resident.
#define ZPT 8
__global__ void __launch_bounds__(128, 12) bp3d_kernel(
    const float* __restrict__ prelu, float* __restrict__ out)
{
    __shared__ float2 strig[N_PROJ];
    if (threadIdx.x < N_PROJ) strig[threadIdx.x] = g_beta[threadIdx.x];
    __syncthreads();

    const int x  = threadIdx.x;
    const int y  = blockIdx.x;
    const int z0 = blockIdx.y * ZPT;

    const float xs = (float)x - 63.5f;
    const float ys = (float)y - 63.5f;
    const float zb = (float)z0 - 63.5f;
    const float KU = 1000.0f / 3.5f;       // DSD/DU == DSD/DV

    float acc[ZPT];
#pragma unroll
    for (int j = 0; j < ZPT; j++) acc[j] = 0.f;

    for (int b = 0; b < N_PROJ; b++) {
        float2 t2 = strig[b];
        float cb = t2.x, sb = t2.y;
        float t = fmaf(xs, cb, ys * sb);
        float s = fmaf(ys, cb, -xs * sb);
        float r   = t + 500.0f;
        float inv = 1.0f / r;
        float pu  = fmaf(s * inv, KU, 63.5f);
        int   iu0 = __float2int_rd(pu);
        float fu  = pu - (float)iu0;
        float m   = 1000.0f * inv;
        float w2  = m * m;                 // (DSD/r)^2 folded into u-weights
        float wu0 = (1.0f - fu) * w2;
        float wu1 = fu * w2;
        float pvk = KU * inv;
        float pv0 = fmaf(pvk, zb, 63.5f);

        const float2* pr = g_cb2 + (b << 14) + iu0;
#pragma unroll
        for (int j = 0; j < ZPT; j++) {
            float pv  = fmaf(pvk, (float)j, pv0);
            int   iv0 = __float2int_rd(pv);
            float fv  = pv - (float)iv0;
            const float2* q = pr + (iv0 << 7);
            float2 r0 = q[0];
            float2 r1 = q[128];
            float h0 = fmaf(r0.y, wu1, r0.x * wu0);
            float h1 = fmaf(r1.y, wu1, r1.x * wu0);
            acc[j] = fmaf(fv, h1 - h0, acc[j] + h0);
        }
    }

    float alpha = prelu[0];
#pragma unroll
    for (int j = 0; j < ZPT; j++) {
        float v = acc[j];
        out[((z0 + j) * HH + y) * WW + x] = (v >= 0.f) ? v : alpha * v;
    }
}

// ---------------- launch ----------------------------------------------------
extern "C" void kernel_launch(void* const* d_in, const int* in_sizes, int n_in,
                              void* d_out, int out_size)
{
    const float* sino  = (const float*)d_in[0];
    const float* wt    = (const float*)d_in[1];
    const float* prelu = (const float*)d_in[2];
    float* out = (float*)d_out;

    beta_kernel<<<1, 96>>>();
    deriv_kernel<<<N_PROJ * A2D, DET2D>>>(sino, wt);
    bp2d_kernel<<<dim3(8, N_PROJ), 256>>>();
    bp3d_kernel<<<dim3(128, ZD / ZPT), 128>>>(prelu, out);
}

// round 6
// speedup vs baseline: 1.1272x; 1.1272x over previous
#include <cuda_runtime.h>
#include <math.h>

#define N_PROJ 96
#define A2D    96
#define DET2D  192
#define HH     128
#define WW     128
#define ZD     128

// ---------------- scratch (device globals; no allocation allowed) ----------
__device__ float4 g_deriv[(N_PROJ * A2D * DET2D) / 4];   // 6.75 MB
__device__ float2 g_cb2[N_PROJ * HH * WW];               // paired layout, 12.6 MB
__device__ float2 g_beta[N_PROJ];                        // (cos, sin) per beta

// ---------------- K0: beta trig table --------------------------------------
__global__ void beta_kernel() {
    int t = threadIdx.x;
    if (t < N_PROJ) {
        float b = (float)t * (float)(2.0 * M_PI / 96.0);
        float s, c;
        sincosf(b, &s, &c);
        g_beta[t] = make_float2(c, s);
    }
}

// ---------------- K1: ws = sino*weight ; deriv along detector --------------
__global__ void __launch_bounds__(192) deriv_kernel(
    const float* __restrict__ sino, const float* __restrict__ wt)
{
    __shared__ float ws[DET2D];
    int row = blockIdx.x;          // 0 .. 96*96-1
    int d = threadIdx.x;           // 0 .. 191
    int idx = row * DET2D + d;
    ws[d] = sino[idx] * wt[idx];
    __syncthreads();
    float v;
    if (d == 0)            v = ws[1] - ws[0];
    else if (d == DET2D-1) v = ws[DET2D-1] - ws[DET2D-2];
    else                   v = 0.5f * (ws[d+1] - ws[d-1]);
    ((float*)g_deriv)[idx] = v;
}

// ---------------- K2: 2D fan backprojection + cosine weights ---------------
// All sample positions are provably in-bounds: pos in [5.7, 185.3].
__global__ void __launch_bounds__(256) bp2d_kernel()
{
    __shared__ float  sder[48 * DET2D];   // 36 KB: half the angles per phase
    __shared__ float2 strig[A2D];

    const int tid = threadIdx.x;
    const int p   = blockIdx.y;          // projection index
    const int y0  = blockIdx.x * 16;     // 16 image rows per CTA

    if (tid < A2D) {
        float th = (float)tid * (float)(M_PI / 96.0);
        float s, c;
        sincosf(th, &s, &c);
        strig[tid] = make_float2(c, s);
    }

    float acc[8], xsv[8], ysv[8];
#pragma unroll
    for (int k = 0; k < 8; k++) {
        int px = tid + k * 256;
        int x  = px & 127;
        int yy = y0 + (px >> 7);
        xsv[k] = (float)x  - 63.5f;
        ysv[k] = (float)yy - 63.5f;
        acc[k] = 0.f;
    }

    const float4* gsrc = g_deriv + p * (A2D * DET2D / 4);

    for (int ph = 0; ph < 2; ph++) {
        __syncthreads();
#pragma unroll
        for (int i = 0; i < 9; i++)
            ((float4*)sder)[tid + i * 256] = gsrc[ph * 2304 + tid + i * 256];
        __syncthreads();

        for (int a = 0; a < 48; a++) {
            float2 t2 = strig[ph * 48 + a];
            float ca = t2.x, sa = t2.y;
            const float* rowp = sder + a * DET2D;
#pragma unroll
            for (int k = 0; k < 8; k++) {
                float pos = fmaf(ca, xsv[k], fmaf(sa, ysv[k], 95.5f));
                int   i0  = __float2int_rd(pos);
                float f   = pos - (float)i0;
                float v0 = rowp[i0];
                float v1 = rowp[i0 + 1];
                acc[k] = fmaf(f, v1 - v0, acc[k] + v0);
            }
        }
    }

    float* cbf = (float*)g_cb2;
#pragma unroll
    for (int k = 0; k < 8; k++) {
        int px = tid + k * 256;
        int x  = px & 127;
        int yy = y0 + (px >> 7);
        float w3  = 1000.0f / sqrtf(1.0e6f + xsv[k]*xsv[k] + ysv[k]*ysv[k]);
        float val = acc[k] * w3;
        int idx = (p * HH + yy) * WW + x;
        cbf[2 * idx] = val;                 // pair[x].x = v[x]
        if (x > 0)    cbf[2 * idx - 1] = val;   // pair[x-1].y = v[x]
        if (x == 127) cbf[2 * idx + 1] = 0.f;   // never read; keep defined
    }
}

// ---------------- K3: 3D cone-beam backprojection + PReLU ------------------
// pu in [11.3,115.7], pv in [19.2,107.7]: mask/clamp free; iu1=iu0+1, iv1=iv0+1.
// pvk = (DSD/DV)/r in [0.455, 0.768] < 1, so along the z-unroll iv0 advances
// by 0 or 1 per step -> incremental row-walk: keep the u-interpolated row pair
// (h0,h1) in registers, advance by data-path selects, ONE unconditional LDG.64
// per z-step (reload of the hot upper row when no advance; identical result).
#define ZPT 8
__global__ void __launch_bounds__(128, 12) bp3d_kernel(
    const float* __restrict__ prelu, float* __restrict__ out)
{
    __shared__ float2 strig[N_PROJ];
    if (threadIdx.x < N_PROJ) strig[threadIdx.x] = g_beta[threadIdx.x];
    __syncthreads();

    const int x  = threadIdx.x;
    const int y  = blockIdx.x;
    const int z0 = blockIdx.y * ZPT;

    const float xs = (float)x - 63.5f;
    const float ys = (float)y - 63.5f;
    const float zb = (float)z0 - 63.5f;
    const float KU = 1000.0f / 3.5f;       // DSD/DU == DSD/DV

    float acc[ZPT];
#pragma unroll
    for (int j = 0; j < ZPT; j++) acc[j] = 0.f;

    for (int b = 0; b < N_PROJ; b++) {
        float2 t2 = strig[b];
        float cb = t2.x, sb = t2.y;
        float t = fmaf(xs, cb, ys * sb);
        float s = fmaf(ys, cb, -xs * sb);
        float r   = t + 500.0f;
        float inv = 1.0f / r;
        float pu  = fmaf(s * inv, KU, 63.5f);
        int   iu0 = __float2int_rd(pu);
        float fu  = pu - (float)iu0;
        float m   = 1000.0f * inv;
        float w2  = m * m;                 // (DSD/r)^2 folded into u-weights
        float wu0 = (1.0f - fu) * w2;
        float wu1 = fu * w2;
        float pvk = KU * inv;
        float pv0 = fmaf(pvk, zb, 63.5f);

        int   iv0 = __float2int_rd(pv0);
        float fv  = pv0 - (float)iv0;

        const char* row = (const char*)(g_cb2 + (b << 14) + iu0) + (iv0 << 10);
        float2 r0 = *(const float2*)row;
        float2 r1 = *(const float2*)(row + 1024);
        float h0 = fmaf(r0.y, wu1, r0.x * wu0);
        float h1 = fmaf(r1.y, wu1, r1.x * wu0);

#pragma unroll
        for (int j = 0; j < ZPT; j++) {
            acc[j] = fmaf(fv, h1 - h0, acc[j] + h0);
            if (j < ZPT - 1) {
                float fvn = fv + pvk;
                bool  adv = (fvn >= 1.0f);
                fv  = adv ? fvn - 1.0f : fvn;
                row = adv ? row + 1024 : row;
                h0  = adv ? h1 : h0;
                float2 rn = *(const float2*)(row + 1024);
                h1 = fmaf(rn.y, wu1, rn.x * wu0);
            }
        }
    }

    float alpha = prelu[0];
#pragma unroll
    for (int j = 0; j < ZPT; j++) {
        float v = acc[j];
        out[((z0 + j) * HH + y) * WW + x] = (v >= 0.f) ? v : alpha * v;
    }
}

// ---------------- launch ----------------------------------------------------
extern "C" void kernel_launch(void* const* d_in, const int* in_sizes, int n_in,
                              void* d_out, int out_size)
{
    const float* sino  = (const float*)d_in[0];
    const float* wt    = (const float*)d_in[1];
    const float* prelu = (const float*)d_in[2];
    float* out = (float*)d_out;

    beta_kernel<<<1, 96>>>();
    deriv_kernel<<<N_PROJ * A2D, DET2D>>>(sino, wt);
    bp2d_kernel<<<dim3(8, N_PROJ), 256>>>();
    bp3d_kernel<<<dim3(128, ZD / ZPT), 128>>>(prelu, out);
}